// round 5
// baseline (speedup 1.0000x reference)
#include <cuda_runtime.h>
#include <math.h>

#define LL 4
#define BB 8
#define NS 1200
#define NL 128
#define CC 768
#define HH 448
#define WW 448
#define GS 56            // 448/8
#define GL 16            // 448/28
#define NBLK_S (LL*NS)   // 4800 blocks, one per (l,n) small-scale
#define NBLK_L (LL*NL)   // 512 blocks, one per (l,n) large-scale
#define NGRP   (2*LL*BB) // 64 accumulator groups (scale, l, b)

// Deterministic accumulators (zero-initialized at module load; final kernel
// resets them after consuming -> correct on every graph replay).
__device__ unsigned long long g_sum_pos[NGRP];
__device__ unsigned long long g_sum_neg[NGRP];
__device__ unsigned int       g_cnt_pos[NGRP];
__device__ unsigned int       g_cnt_neg[NGRP];

#define FIXED_SCALE 4294967296.0   // 2^32

// ---------------------------------------------------------------------------
// Kernel 1: fully fused. Block = one (scale, l, n) column; warp w = batch b.
// Each warp: distance over 768 floats + nonzero flag; shared OR gives
// col_valid; lane 0 gathers membership early and atomically accumulates.
__global__ void __launch_bounds__(256, 4) patch_fused(
        const float* __restrict__ sel_s, const int* __restrict__ idx_s,
        const float* __restrict__ sel_l, const int* __restrict__ idx_l,
        const float* __restrict__ ker_s, const float* __restrict__ ker_l,
        const float* __restrict__ fk) {
    int blk  = blockIdx.x;
    int wid  = threadIdx.x >> 5;      // = b
    int lane = threadIdx.x & 31;

    const float* sel; const float* ker; const int* idxA;
    int l, n, N, scale;
    if (blk < NBLK_S) {
        scale = 0; N = NS; l = blk / NS; n = blk % NS;
        sel = sel_s; ker = ker_s; idxA = idx_s;
    } else {
        scale = 1; N = NL; l = (blk - NBLK_S) / NL; n = (blk - NBLK_S) % NL;
        sel = sel_l; ker = ker_l; idxA = idx_l;
    }
    int b   = wid;
    int row = (l*BB + b)*N + n;

    // Early membership gather (lane 0 only): idx -> f_k pixel. Latency hidden
    // behind the streaming vector loads below.
    bool member = false;
    if (lane == 0) {
        int idx = idxA[row];
        int gy, gx;
        if (scale == 0) { gy = idx / GS; gx = idx % GS;
            member = fk[(size_t)b*HH*WW + (size_t)gy*8*WW + gx*8] > 0.f; }
        else            { gy = idx / GL; gx = idx % GL;
            member = fk[(size_t)b*HH*WW + (size_t)gy*28*WW + gx*28] > 0.f; }
    }

    const float4* s4 = reinterpret_cast<const float4*>(sel) + (size_t)row     * (CC/4);
    const float4* k4 = reinterpret_cast<const float4*>(ker) + (size_t)(l*BB+b)* (CC/4);

    float4 sv[6], kv[6];
    #pragma unroll
    for (int i = 0; i < 6; i++) sv[i] = __ldcs(&s4[lane + 32*i]);   // streaming DRAM
    #pragma unroll
    for (int i = 0; i < 6; i++) kv[i] = __ldg(&k4[lane + 32*i]);    // L1/L2-resident

    float acc = 0.f;
    unsigned orb = 0u;
    #pragma unroll
    for (int i = 0; i < 6; i++) {
        float d0 = kv[i].x - sv[i].x, d1 = kv[i].y - sv[i].y;
        float d2 = kv[i].z - sv[i].z, d3 = kv[i].w - sv[i].w;
        acc = fmaf(d0, d0, acc); acc = fmaf(d1, d1, acc);
        acc = fmaf(d2, d2, acc); acc = fmaf(d3, d3, acc);
        orb |= __float_as_uint(sv[i].x) | __float_as_uint(sv[i].y)
             | __float_as_uint(sv[i].z) | __float_as_uint(sv[i].w);
    }
    #pragma unroll
    for (int o = 16; o; o >>= 1) {
        acc += __shfl_xor_sync(0xffffffffu, acc, o);
        orb |= __shfl_xor_sync(0xffffffffu, orb, o);
    }

    // col_valid = OR of nz over the block's 8 warps (all b of this (l,n))
    __shared__ unsigned char s_nz[8];
    if (lane == 0) s_nz[wid] = ((orb & 0x7fffffffu) != 0u) ? 1 : 0;
    __syncthreads();
    if (lane == 0) {
        unsigned cv = 0;
        #pragma unroll
        for (int i = 0; i < 8; i++) cv |= s_nz[i];
        if (cv) {
            float d = sqrtf(acc);
            unsigned long long q = (unsigned long long)((double)d * FIXED_SCALE);
            int g = scale*LL*BB + l*BB + b;
            if (member) { atomicAdd(&g_sum_pos[g], q); atomicAdd(&g_cnt_pos[g], 1u); }
            else        { atomicAdd(&g_sum_neg[g], q); atomicAdd(&g_cnt_neg[g], 1u); }
        }
    }
}

// ---------------------------------------------------------------------------
// Kernel 2: final scalar from 64 groups. Also resets accumulators for the
// next graph replay (each thread resets only the slots it consumed).
__global__ void final_kernel(float* __restrict__ out) {
    int t = (int)threadIdx.x;   // 0..63
    unsigned long long sp = g_sum_pos[t], sn = g_sum_neg[t];
    unsigned int       cp = g_cnt_pos[t], cn = g_cnt_neg[t];
    // reset for next replay
    g_sum_pos[t] = 0ull; g_sum_neg[t] = 0ull;
    g_cnt_pos[t] = 0u;   g_cnt_neg[t] = 0u;

    float ap = (float)((double)sp / FIXED_SCALE / (double)max(cp, 1u));
    float an = (float)((double)sn / FIXED_SCALE / (double)max(cn, 1u));
    float x = ap - an;
    float loss = fmaxf(x, 0.f) + log1pf(expf(-fabsf(x)));   // stable softplus
    int act = (cp > 0u && cn > 0u) ? 1 : 0;

    __shared__ float s_loss[64];
    __shared__ int   s_act[64];
    s_loss[t] = loss; s_act[t] = act;
    __syncthreads();
    if (t < 32) {
        int   as  = s_act[t];
        int   al  = s_act[32 + t] & as;        // act_l &= act_s
        float tot = (as ? s_loss[t] : 0.f) + (al ? s_loss[32 + t] : 0.f);
        int times = as + al;
        #pragma unroll
        for (int o = 16; o; o >>= 1) {
            tot   += __shfl_xor_sync(0xffffffffu, tot, o);
            times += __shfl_xor_sync(0xffffffffu, times, o);
        }
        if (t == 0) out[0] = (times > 0) ? tot / (float)times : 0.f;
    }
}

// ---------------------------------------------------------------------------
extern "C" void kernel_launch(void* const* d_in, const int* in_sizes, int n_in,
                              void* d_out, int out_size) {
    const float* sel_s = (const float*)d_in[0];
    const int*   idx_s = (const int*)  d_in[1];
    const float* sel_l = (const float*)d_in[2];
    const int*   idx_l = (const int*)  d_in[3];
    const float* ker_s = (const float*)d_in[4];
    const float* ker_l = (const float*)d_in[5];
    const float* fk    = (const float*)d_in[6];

    patch_fused<<<NBLK_S + NBLK_L, 256>>>(sel_s, idx_s, sel_l, idx_l,
                                          ker_s, ker_l, fk);
    final_kernel<<<1, 64>>>((float*)d_out);
}

// round 6
// speedup vs baseline: 1.3381x; 1.3381x over previous
#include <cuda_runtime.h>
#include <math.h>

#define LL 4
#define BB 8
#define NS 1200
#define NL 128
#define CC 768
#define HH 448
#define WW 448
#define GS 56            // 448/8
#define GL 16            // 448/28
#define NROW_S (LL*BB*NS)    // 38400
#define NROW_L (LL*BB*NL)    // 4096
#define NPAIR_S (NROW_S/2)   // 19200
#define NPAIR_L (NROW_L/2)   // 2048
#define CHUNK_S 240          // 1200 = 5 * 240
#define NCHUNK_S 5
#define NBLK_STATS (LL*BB*NCHUNK_S + LL*BB)   // 160 + 32 = 192

// Scratch (no allocation allowed)
__device__ float         g_d_s[NROW_S];
__device__ float         g_d_l[NROW_L];
__device__ unsigned char g_nzT_s[LL*NS*BB];   // [l][n][b] -> 8B aligned per (l,n)
__device__ unsigned char g_nzT_l[LL*NL*BB];
__device__ float g_sp[NBLK_STATS], g_sn[NBLK_STATS];
__device__ int   g_cp[NBLK_STATS], g_cn[NBLK_STATS];

// ---------------------------------------------------------------------------
// Kernel 1: per-row distance + nonzero flag, 2 consecutive rows per warp.
// 12 independent streaming LDG.128 per lane -> high MLP; kernel vector loaded
// once and reused for both rows (same lb).
__global__ void dist_fused(const float* __restrict__ sel_s,
                           const float* __restrict__ ker_s,
                           const float* __restrict__ sel_l,
                           const float* __restrict__ ker_l) {
    int p    = blockIdx.x * 8 + (threadIdx.x >> 5);   // pair index
    int lane = threadIdx.x & 31;

    const float* sel; const float* ker;
    float* dOut; unsigned char* nzT;
    int N, r0;
    if (p < NPAIR_S) {
        r0 = 2*p; N = NS; sel = sel_s; ker = ker_s; dOut = g_d_s; nzT = g_nzT_s;
    } else {
        int pl = p - NPAIR_S;
        if (pl >= NPAIR_L) return;
        r0 = 2*pl; N = NL; sel = sel_l; ker = ker_l; dOut = g_d_l; nzT = g_nzT_l;
    }
    int lb = r0 / N, n0 = r0 % N;     // r0 even, N even -> r0,r0+1 share lb
    int l = lb / BB, b = lb % BB;

    const float4* s4 = reinterpret_cast<const float4*>(sel) + (size_t)r0 * (CC/4);
    const float4* k4 = reinterpret_cast<const float4*>(ker) + (size_t)lb * (CC/4);

    float4 sv0[6], sv1[6], kv[6];
    #pragma unroll
    for (int i = 0; i < 6; i++) sv0[i] = s4[lane + 32*i];            // row r0
    #pragma unroll
    for (int i = 0; i < 6; i++) sv1[i] = s4[(CC/4) + lane + 32*i];   // row r0+1
    #pragma unroll
    for (int i = 0; i < 6; i++) kv[i]  = __ldg(&k4[lane + 32*i]);    // L1/L2-resident

    float a0 = 0.f, a1 = 0.f;
    unsigned o0 = 0u, o1 = 0u;
    #pragma unroll
    for (int i = 0; i < 6; i++) {
        float d0 = kv[i].x - sv0[i].x, d1 = kv[i].y - sv0[i].y;
        float d2 = kv[i].z - sv0[i].z, d3 = kv[i].w - sv0[i].w;
        a0 = fmaf(d0, d0, a0); a0 = fmaf(d1, d1, a0);
        a0 = fmaf(d2, d2, a0); a0 = fmaf(d3, d3, a0);
        o0 |= __float_as_uint(sv0[i].x) | __float_as_uint(sv0[i].y)
            | __float_as_uint(sv0[i].z) | __float_as_uint(sv0[i].w);
        float e0 = kv[i].x - sv1[i].x, e1 = kv[i].y - sv1[i].y;
        float e2 = kv[i].z - sv1[i].z, e3 = kv[i].w - sv1[i].w;
        a1 = fmaf(e0, e0, a1); a1 = fmaf(e1, e1, a1);
        a1 = fmaf(e2, e2, a1); a1 = fmaf(e3, e3, a1);
        o1 |= __float_as_uint(sv1[i].x) | __float_as_uint(sv1[i].y)
            | __float_as_uint(sv1[i].z) | __float_as_uint(sv1[i].w);
    }
    #pragma unroll
    for (int o = 16; o; o >>= 1) {
        a0 += __shfl_xor_sync(0xffffffffu, a0, o);
        a1 += __shfl_xor_sync(0xffffffffu, a1, o);
        o0 |= __shfl_xor_sync(0xffffffffu, o0, o);
        o1 |= __shfl_xor_sync(0xffffffffu, o1, o);
    }
    if (lane == 0) {
        dOut[r0]     = sqrtf(a0);
        dOut[r0 + 1] = sqrtf(a1);
        nzT[(size_t)(l*N + n0    )*BB + b] = ((o0 & 0x7fffffffu) != 0u) ? 1 : 0;
        nzT[(size_t)(l*N + n0 + 1)*BB + b] = ((o1 & 0x7fffffffu) != 0u) ? 1 : 0;
    }
}

// ---------------------------------------------------------------------------
// Kernel 2: partial masked sums. Blocks [0,160): scale s (5 chunks of 240 per
// (l,b)); blocks [160,192): scale l. col_valid = one 8-byte load; membership
// = direct f_k gather.
__global__ void __launch_bounds__(256) stats_partial(const int* __restrict__ idx_s,
                                                     const int* __restrict__ idx_l,
                                                     const float* __restrict__ fk) {
    int blk = blockIdx.x;
    bool is_s = blk < LL*BB*NCHUNK_S;
    int g, n0, nCnt;
    if (is_s) { g = blk / NCHUNK_S; n0 = (blk % NCHUNK_S) * CHUNK_S; nCnt = CHUNK_S; }
    else      { g = blk - LL*BB*NCHUNK_S; n0 = 0; nCnt = NL; }
    int l = g / BB, b = g % BB;

    float sp = 0.f, sn = 0.f;
    int cp = 0, cn = 0;
    int t = (int)threadIdx.x;
    if (t < nCnt) {
        int n = n0 + t;
        unsigned long long nz64;
        float d; int idx; bool member;
        if (is_s) {
            nz64 = *reinterpret_cast<const unsigned long long*>(g_nzT_s + (size_t)(l*NS + n)*8);
            d    = g_d_s[g*NS + n];
            idx  = idx_s[g*NS + n];
            int gy = idx / GS, gx = idx % GS;
            member = fk[(size_t)b*HH*WW + (size_t)gy*8*WW + gx*8] > 0.f;
        } else {
            nz64 = *reinterpret_cast<const unsigned long long*>(g_nzT_l + (size_t)(l*NL + n)*8);
            d    = g_d_l[g*NL + n];
            idx  = idx_l[g*NL + n];
            int gy = idx / GL, gx = idx % GL;
            member = fk[(size_t)b*HH*WW + (size_t)gy*28*WW + gx*28] > 0.f;
        }
        if (nz64 != 0ull) {
            if (member) { sp = d; cp = 1; } else { sn = d; cn = 1; }
        }
    }
    #pragma unroll
    for (int o = 16; o; o >>= 1) {
        sp += __shfl_xor_sync(0xffffffffu, sp, o);
        sn += __shfl_xor_sync(0xffffffffu, sn, o);
        cp += __shfl_xor_sync(0xffffffffu, cp, o);
        cn += __shfl_xor_sync(0xffffffffu, cn, o);
    }
    __shared__ float s_sp[8], s_sn[8];
    __shared__ int   s_cp[8], s_cn[8];
    int wid = t >> 5, ln = t & 31;
    if (ln == 0) { s_sp[wid] = sp; s_sn[wid] = sn; s_cp[wid] = cp; s_cn[wid] = cn; }
    __syncthreads();
    if (t == 0) {
        float tsp = 0.f, tsn = 0.f; int tcp = 0, tcn = 0;
        #pragma unroll
        for (int wI = 0; wI < 8; wI++) { tsp += s_sp[wI]; tsn += s_sn[wI]; tcp += s_cp[wI]; tcn += s_cn[wI]; }
        g_sp[blk] = tsp; g_sn[blk] = tsn; g_cp[blk] = tcp; g_cn[blk] = tcn;
    }
}

// ---------------------------------------------------------------------------
// Kernel 3: finish. 64 threads: t<32 -> s-group t (sum 5 chunk slots),
// t>=32 -> l-group t-32 (one slot). Then combine pairs, reduce, write scalar.
__global__ void final_kernel(float* __restrict__ out) {
    int t = (int)threadIdx.x;   // 0..63
    float sp = 0.f, sn = 0.f; int cp = 0, cn = 0;
    if (t < 32) {
        #pragma unroll
        for (int c = 0; c < NCHUNK_S; c++) {
            int s = t*NCHUNK_S + c;
            sp += g_sp[s]; sn += g_sn[s]; cp += g_cp[s]; cn += g_cn[s];
        }
    } else {
        int s = LL*BB*NCHUNK_S + (t - 32);
        sp = g_sp[s]; sn = g_sn[s]; cp = g_cp[s]; cn = g_cn[s];
    }
    float ap = sp / (float)max(cp, 1);
    float an = sn / (float)max(cn, 1);
    float x = ap - an;
    float loss = fmaxf(x, 0.f) + log1pf(expf(-fabsf(x)));   // stable softplus
    int act = (cp > 0 && cn > 0) ? 1 : 0;

    __shared__ float s_loss[64];
    __shared__ int   s_act[64];
    s_loss[t] = loss; s_act[t] = act;
    __syncthreads();
    if (t < 32) {
        int   as  = s_act[t];
        int   al  = s_act[32 + t] & as;        // act_l &= act_s
        float tot = (as ? s_loss[t] : 0.f) + (al ? s_loss[32 + t] : 0.f);
        int times = as + al;
        #pragma unroll
        for (int o = 16; o; o >>= 1) {
            tot   += __shfl_xor_sync(0xffffffffu, tot, o);
            times += __shfl_xor_sync(0xffffffffu, times, o);
        }
        if (t == 0) out[0] = (times > 0) ? tot / (float)times : 0.f;
    }
}

// ---------------------------------------------------------------------------
extern "C" void kernel_launch(void* const* d_in, const int* in_sizes, int n_in,
                              void* d_out, int out_size) {
    const float* sel_s = (const float*)d_in[0];
    const int*   idx_s = (const int*)  d_in[1];
    const float* sel_l = (const float*)d_in[2];
    const int*   idx_l = (const int*)  d_in[3];
    const float* ker_s = (const float*)d_in[4];
    const float* ker_l = (const float*)d_in[5];
    const float* fk    = (const float*)d_in[6];

    int nblk = (NPAIR_S + NPAIR_L + 7) / 8;   // 8 warps (pairs) per block
    dist_fused<<<nblk, 256>>>(sel_s, ker_s, sel_l, ker_l);
    stats_partial<<<NBLK_STATS, 256>>>(idx_s, idx_l, fk);
    final_kernel<<<1, 64>>>((float*)d_out);
}